// round 4
// baseline (speedup 1.0000x reference)
#include <cuda_runtime.h>

// ============================================================================
// AdditiveAttention: out = softmax_k( sum_h w_v[h]*tanh(qW_q + kW_k) ) @ V
// B=16, NQ=64, NK=512, QS=KS=H=VD=256, fp32.
//
// Identity used:  tanh(x) = 1 - 2*r,  r = 1/(1+e^{2x})
//   score(q,k) = sum_h w_v[h]*tanh(.) = (sum_h w_v[h]) - sum_h (2*w_v[h])*r_h
// We fold the 2*log2(e) factor for ex2 into the projection outputs, so the
// inner loop per element is: FADD, MUFU.EX2, FADD, MUFU.RCP, FFMA  (MUFU-bound).
// ============================================================================

#define C2SCALE 2.885390081777927f   // 2*log2(e)

// scratch (allocation-free rule -> __device__ globals)
__device__ float g_qh[16 * 64 * 256];    // 4 MB: C2 * (queries @ W_q)
__device__ float g_kh[16 * 512 * 256];   // 8 MB: C2 * (keys @ W_k)

__device__ __forceinline__ float ex2_fast(float x) {
    float r; asm("ex2.approx.f32 %0, %1;" : "=f"(r) : "f"(x)); return r;
}
__device__ __forceinline__ float rcp_fast(float x) {
    float r; asm("rcp.approx.f32 %0, %1;" : "=f"(r) : "f"(x)); return r;
}

// ----------------------------------------------------------------------------
// Projection SGEMM: C[M,256] = scale * (A[M,256] @ W[256,256])
// BM=BN=64, BK=16, 256 threads, 4x4 micro-tile per thread.
// ----------------------------------------------------------------------------
__global__ __launch_bounds__(256)
void proj_kernel(const float* __restrict__ A,
                 const float* __restrict__ W,
                 float* __restrict__ Cout,
                 float scale) {
    __shared__ float As[16][68];   // [k][m], padded
    __shared__ float Ws[16][68];   // [k][n], padded

    const int tid  = threadIdx.x;
    const int tx   = tid & 15;        // n-thread
    const int ty   = tid >> 4;        // m-thread
    const int bm   = blockIdx.y * 64;
    const int bn   = blockIdx.x * 64;
    const int lrow = tid >> 2;        // 0..63  A-load row
    const int lk   = (tid & 3) * 4;   // A-load k offset
    const int wrow = tid >> 4;        // 0..15  W-load k row
    const int wcol = (tid & 15) * 4;  // W-load n offset

    float acc[4][4] = {};

    for (int k0 = 0; k0 < 256; k0 += 16) {
        float4 av = *(const float4*)&A[(bm + lrow) * 256 + k0 + lk];
        float4 wv = *(const float4*)&W[(k0 + wrow) * 256 + bn + wcol];
        As[lk + 0][lrow] = av.x;
        As[lk + 1][lrow] = av.y;
        As[lk + 2][lrow] = av.z;
        As[lk + 3][lrow] = av.w;
        *(float4*)&Ws[wrow][wcol] = wv;
        __syncthreads();

        #pragma unroll
        for (int kk = 0; kk < 16; ++kk) {
            float4 a4 = *(const float4*)&As[kk][ty * 4];
            float4 b4 = *(const float4*)&Ws[kk][tx * 4];
            float a[4] = {a4.x, a4.y, a4.z, a4.w};
            float b[4] = {b4.x, b4.y, b4.z, b4.w};
            #pragma unroll
            for (int i = 0; i < 4; ++i)
                #pragma unroll
                for (int j = 0; j < 4; ++j)
                    acc[i][j] = fmaf(a[i], b[j], acc[i][j]);
        }
        __syncthreads();
    }

    #pragma unroll
    for (int i = 0; i < 4; ++i) {
        float4 o = make_float4(acc[i][0] * scale, acc[i][1] * scale,
                               acc[i][2] * scale, acc[i][3] * scale);
        *(float4*)&Cout[(bm + ty * 4 + i) * 256 + bn + tx * 4] = o;
    }
}

// ----------------------------------------------------------------------------
// Fused scores + masked softmax + attn@V.
// Grid: 128 blocks = (b, 8-query tile).  Block: 512 threads = 16 warps.
// Warp w: query qloc = w>>1, key half sub = w&1.  Lane l owns key
// k = t*64 + sub*32 + l over 8 smem tiles of 64 keys -> 256 keys/warp,
// scores fully lane-resident (no shuffles in hot loop).
// ----------------------------------------------------------------------------
#define KH_STRIDE 260   // pad: 260 % 32 == 4 -> conflict-free LDS.128; 1040B rows stay 16B-aligned
#define ATTN_SMEM_FLOATS (64 * KH_STRIDE + 8 * 256 + 256 + 8 * 512 + 32)
#define ATTN_SMEM_BYTES  (ATTN_SMEM_FLOATS * 4)

__global__ __launch_bounds__(512, 1)
void attn_kernel(const float* __restrict__ values,
                 const int* __restrict__ valid_lens,
                 const float* __restrict__ w_v,
                 float* __restrict__ out) {
    extern __shared__ float sm[];
    float* kh_s   = sm;                         // 64 x 260
    float* qh_s   = kh_s + 64 * KH_STRIDE;      // 8 x 256
    float* w2_s   = qh_s + 8 * 256;             // 256  (= 2*w_v)
    float* attn_s = w2_s + 256;                 // 8 x 512
    float* red_s  = attn_s + 8 * 512;           // [0..15] max, [16..31] sum

    const int tid  = threadIdx.x;
    const int b    = blockIdx.x >> 3;
    const int q0   = (blockIdx.x & 7) * 8;
    const int w    = tid >> 5;
    const int lane = tid & 31;
    const int qloc = w >> 1;
    const int sub  = w & 1;
    const int krow = sub * 32 + lane;
    const int vlen = valid_lens[b];

    // stage 8 query rows (already pre-scaled by 2*log2e) and 2*w_v
    for (int i = tid; i < 8 * 256; i += 512)
        qh_s[i] = g_qh[(b * 64 + q0) * 256 + i];
    for (int i = tid; i < 256; i += 512)
        w2_s[i] = 2.0f * w_v[i];

    float sc[8];

    #pragma unroll
    for (int t = 0; t < 8; ++t) {
        __syncthreads();
        // stage 64 key rows (pre-scaled) into padded smem
        const float* src = &g_kh[((size_t)b * 512 + t * 64) * 256];
        for (int i = tid; i < 64 * 64; i += 512) {
            int r = i >> 6, c = (i & 63) << 2;
            *(float4*)&kh_s[r * KH_STRIDE + c] = *(const float4*)&src[r * 256 + c];
        }
        __syncthreads();

        const float* khr = &kh_s[krow * KH_STRIDE];
        const float* qr  = &qh_s[qloc * 256];
        float s0 = 0.f, s1 = 0.f;
        #pragma unroll 8
        for (int h = 0; h < 256; h += 4) {
            float4 kv = *(const float4*)&khr[h];
            float4 qv = *(const float4*)&qr[h];
            float4 w4 = *(const float4*)&w2_s[h];
            s0 = fmaf(w4.x, rcp_fast(1.0f + ex2_fast(qv.x + kv.x)), s0);
            s1 = fmaf(w4.y, rcp_fast(1.0f + ex2_fast(qv.y + kv.y)), s1);
            s0 = fmaf(w4.z, rcp_fast(1.0f + ex2_fast(qv.z + kv.z)), s0);
            s1 = fmaf(w4.w, rcp_fast(1.0f + ex2_fast(qv.w + kv.w)), s1);
        }
        sc[t] = s0 + s1;       // = sum_h 2*w_v*r   (score = wvsum - this)
    }

    // wvsum = sum_h w_v[h]  (per-warp, trivial)
    float wvsum = 0.f;
    for (int i = lane; i < 256; i += 32) wvsum += w2_s[i];
    #pragma unroll
    for (int o = 16; o; o >>= 1) wvsum += __shfl_xor_sync(0xffffffffu, wvsum, o);
    wvsum *= 0.5f;

    // mask + local max
    float m = -3e38f;
    #pragma unroll
    for (int t = 0; t < 8; ++t) {
        int k = t * 64 + krow;
        float v = wvsum - sc[t];
        if (k >= vlen) v = -1e30f;
        sc[t] = v;
        m = fmaxf(m, v);
    }
    #pragma unroll
    for (int o = 16; o; o >>= 1) m = fmaxf(m, __shfl_xor_sync(0xffffffffu, m, o));
    if (lane == 0) red_s[qloc * 2 + sub] = m;
    __syncthreads();
    const float mall = fmaxf(red_s[qloc * 2], red_s[qloc * 2 + 1]);

    float p[8];
    float sum = 0.f;
    #pragma unroll
    for (int t = 0; t < 8; ++t) {
        p[t] = ex2_fast((sc[t] - mall) * 1.4426950408889634f);
        sum += p[t];
    }
    #pragma unroll
    for (int o = 16; o; o >>= 1) sum += __shfl_xor_sync(0xffffffffu, sum, o);
    if (lane == 0) red_s[16 + qloc * 2 + sub] = sum;
    __syncthreads();
    const float inv = rcp_fast(red_s[16 + qloc * 2] + red_s[16 + qloc * 2 + 1]);

    #pragma unroll
    for (int t = 0; t < 8; ++t)
        attn_s[qloc * 512 + t * 64 + krow] = p[t] * inv;
    __syncthreads();

    // ------ output: out[b, q0+qq, v] = sum_k attn[qq][k] * values[b,k,v] ------
    const int half = tid >> 8;          // 0: q0..q0+3, 1: q0+4..q0+7
    const int v    = tid & 255;
    const float* vp = values + (size_t)b * 512 * 256 + v;
    const float* a0 = &attn_s[(half * 4 + 0) * 512];
    const float* a1 = a0 + 512;
    const float* a2 = a1 + 512;
    const float* a3 = a2 + 512;
    float o0 = 0.f, o1 = 0.f, o2 = 0.f, o3 = 0.f;
    #pragma unroll 4
    for (int k = 0; k < vlen; ++k) {
        float vv = vp[(size_t)k * 256];
        o0 = fmaf(a0[k], vv, o0);
        o1 = fmaf(a1[k], vv, o1);
        o2 = fmaf(a2[k], vv, o2);
        o3 = fmaf(a3[k], vv, o3);
    }
    float* op = out + ((size_t)b * 64 + q0 + half * 4) * 256 + v;
    op[0]   = o0;
    op[256] = o1;
    op[512] = o2;
    op[768] = o3;
}

// ----------------------------------------------------------------------------
extern "C" void kernel_launch(void* const* d_in, const int* in_sizes, int n_in,
                              void* d_out, int out_size) {
    (void)in_sizes; (void)n_in; (void)out_size;
    const float* queries = (const float*)d_in[0];   // [16,64,256]
    const float* keys    = (const float*)d_in[1];   // [16,512,256]
    const float* values  = (const float*)d_in[2];   // [16,512,256]
    const int*   vlens   = (const int*)  d_in[3];   // [16]
    const float* Wq      = (const float*)d_in[4];   // [256,256]
    const float* Wk      = (const float*)d_in[5];   // [256,256]
    const float* wv      = (const float*)d_in[6];   // [256]
    float* out = (float*)d_out;                     // [16,64,256]

    float *qh = nullptr, *kh = nullptr;
    cudaGetSymbolAddress((void**)&qh, g_qh);
    cudaGetSymbolAddress((void**)&kh, g_kh);

    cudaFuncSetAttribute(attn_kernel,
                         cudaFuncAttributeMaxDynamicSharedMemorySize,
                         ATTN_SMEM_BYTES);

    // qh = C2 * queries@Wq  (M=1024), kh = C2 * keys@Wk (M=8192)
    proj_kernel<<<dim3(4, 16), 256>>>(queries, Wq, qh, C2SCALE);
    proj_kernel<<<dim3(4, 128), 256>>>(keys, Wk, kh, C2SCALE);
    attn_kernel<<<128, 512, ATTN_SMEM_BYTES>>>(values, vlens, wv, out);
}

// round 7
// speedup vs baseline: 1.4027x; 1.4027x over previous
#include <cuda_runtime.h>

// ============================================================================
// AdditiveAttention: out = softmax_k( sum_h w_v[h]*tanh(qW_q + kW_k) ) @ V
// B=16, NQ=64, NK=512, QS=KS=H=VD=256, fp32.
//
// R5 = R4 with the cp.async staging index bug fixed:
//   sc4 was (tid&7)*8 -> columns up to 280 (OOB gmem read + smem overrun).
//   Correct: thread j covers float4 indices j + i*8 -> float col j*4 + i*32.
// ============================================================================

// scratch (allocation-free rule -> __device__ globals)
__device__ float g_qh[16 * 64 * 256];    // 4 MB: queries @ W_q
__device__ float g_kh[16 * 512 * 256];   // 8 MB: keys @ W_k

__device__ __forceinline__ float tanh_fast(float x) {
    float r; asm("tanh.approx.f32 %0, %1;" : "=f"(r) : "f"(x)); return r;
}
__device__ __forceinline__ float ex2_fast(float x) {
    float r; asm("ex2.approx.f32 %0, %1;" : "=f"(r) : "f"(x)); return r;
}
__device__ __forceinline__ float rcp_fast(float x) {
    float r; asm("rcp.approx.f32 %0, %1;" : "=f"(r) : "f"(x)); return r;
}
__device__ __forceinline__ void cp_async16(void* smem_dst, const void* gmem_src) {
    unsigned s = (unsigned)__cvta_generic_to_shared(smem_dst);
    asm volatile("cp.async.cg.shared.global [%0], [%1], 16;\n" :: "r"(s), "l"(gmem_src));
}
__device__ __forceinline__ void cp_async_commit() {
    asm volatile("cp.async.commit_group;\n" ::);
}
__device__ __forceinline__ void cp_async_wait1() {
    asm volatile("cp.async.wait_group 1;\n" ::);
}
__device__ __forceinline__ void cp_async_wait0() {
    asm volatile("cp.async.wait_group 0;\n" ::);
}

// ----------------------------------------------------------------------------
// Merged projection SGEMM.
// Logical M = 1024 (queries) + 8192 (keys) = 9216 rows; N = 256, K = 256.
// BM=128, BN=128, BK=16, 256 threads, 8x8 micro-tile.
// Grid = (2, 72) = 144 blocks -> one full wave on 148 SMs.
// ----------------------------------------------------------------------------
#define PJ_PAD 132

__global__ __launch_bounds__(256, 1)
void proj_kernel(const float* __restrict__ queries,
                 const float* __restrict__ keys,
                 const float* __restrict__ Wq,
                 const float* __restrict__ Wk,
                 float* __restrict__ qh,
                 float* __restrict__ kh) {
    __shared__ float As[16 * PJ_PAD];   // [k][m] transposed, padded
    __shared__ float Ws[16 * PJ_PAD];   // [k][n], padded

    const int tid = threadIdx.x;
    const int tx  = tid & 15;          // n-thread: 8 cols each
    const int ty  = tid >> 4;          // m-thread: 8 rows each
    const int bm  = blockIdx.y * 128;
    const int bn  = blockIdx.x * 128;

    const float* A; const float* W; float* C; int rowbase;
    if (bm < 1024) { A = queries; W = Wq; C = qh; rowbase = bm; }
    else           { A = keys;    W = Wk; C = kh; rowbase = bm - 1024; }

    // A load: 128 rows x 16 k = 512 float4, 2 per thread
    const int ar0 = tid >> 2;            // 0..63
    const int ac  = (tid & 3) * 4;       // k offset 0/4/8/12
    // W load: 16 k x 128 n = 512 float4, 2 per thread
    const int wr0 = tid >> 5;            // 0..7
    const int wc  = (tid & 31) * 4;      // n offset

    float acc[8][8] = {};

    for (int k0 = 0; k0 < 256; k0 += 16) {
        float4 a0 = *(const float4*)&A[(rowbase + ar0)      * 256 + k0 + ac];
        float4 a1 = *(const float4*)&A[(rowbase + ar0 + 64) * 256 + k0 + ac];
        float4 w0 = *(const float4*)&W[(k0 + wr0)     * 256 + bn + wc];
        float4 w1 = *(const float4*)&W[(k0 + wr0 + 8) * 256 + bn + wc];

        // transposed store of A: As[k][m]
        As[(ac + 0) * PJ_PAD + ar0]      = a0.x;
        As[(ac + 1) * PJ_PAD + ar0]      = a0.y;
        As[(ac + 2) * PJ_PAD + ar0]      = a0.z;
        As[(ac + 3) * PJ_PAD + ar0]      = a0.w;
        As[(ac + 0) * PJ_PAD + ar0 + 64] = a1.x;
        As[(ac + 1) * PJ_PAD + ar0 + 64] = a1.y;
        As[(ac + 2) * PJ_PAD + ar0 + 64] = a1.z;
        As[(ac + 3) * PJ_PAD + ar0 + 64] = a1.w;
        *(float4*)&Ws[ wr0      * PJ_PAD + wc] = w0;
        *(float4*)&Ws[(wr0 + 8) * PJ_PAD + wc] = w1;
        __syncthreads();

        #pragma unroll
        for (int kk = 0; kk < 16; ++kk) {
            float a[8], b[8];
            *(float4*)&a[0] = *(const float4*)&As[kk * PJ_PAD + ty * 8];
            *(float4*)&a[4] = *(const float4*)&As[kk * PJ_PAD + ty * 8 + 4];
            *(float4*)&b[0] = *(const float4*)&Ws[kk * PJ_PAD + tx * 8];
            *(float4*)&b[4] = *(const float4*)&Ws[kk * PJ_PAD + tx * 8 + 4];
            #pragma unroll
            for (int i = 0; i < 8; ++i)
                #pragma unroll
                for (int j = 0; j < 8; ++j)
                    acc[i][j] = fmaf(a[i], b[j], acc[i][j]);
        }
        __syncthreads();
    }

    #pragma unroll
    for (int i = 0; i < 8; ++i) {
        float* dst = &C[(rowbase + ty * 8 + i) * 256 + bn + tx * 8];
        *(float4*)&dst[0] = *(float4*)&acc[i][0];
        *(float4*)&dst[4] = *(float4*)&acc[i][4];
    }
}

// ----------------------------------------------------------------------------
// Fused scores + masked softmax + attn@V.
// Grid: 128 blocks = (b, 8-query tile).  Block: 512 threads = 16 warps.
// Warp w: query qloc = w>>1, sub = w&1, lane owns key k = t*64 + sub*32 + lane
// over 8 double-buffered cp.async-staged tiles of 64 keys.
// ----------------------------------------------------------------------------
#define KH_STRIDE 260   // 260 % 32 == 4 -> conflict-free LDS.128, rows 16B-aligned
#define ATTN_SMEM_FLOATS (2 * 64 * KH_STRIDE + 8 * 256 + 256 + 8 * 512 + 32)
#define ATTN_SMEM_BYTES  (ATTN_SMEM_FLOATS * 4)

__global__ __launch_bounds__(512, 1)
void attn_kernel(const float* __restrict__ values,
                 const int* __restrict__ valid_lens,
                 const float* __restrict__ w_v,
                 float* __restrict__ out) {
    extern __shared__ float sm[];
    float* kh_s   = sm;                              // 2 x 64 x 260 (double buf)
    float* qh_s   = kh_s + 2 * 64 * KH_STRIDE;       // 8 x 256
    float* wv_s   = qh_s + 8 * 256;                  // 256
    float* attn_s = wv_s + 256;                      // 8 x 512
    float* red_s  = attn_s + 8 * 512;                // [0..15] max, [16..31] sum

    const int tid  = threadIdx.x;
    const int b    = blockIdx.x >> 3;
    const int q0   = (blockIdx.x & 7) * 8;
    const int w    = tid >> 5;
    const int lane = tid & 31;
    const int qloc = w >> 1;
    const int sub  = w & 1;
    const int krow = sub * 32 + lane;
    const int vlen = valid_lens[b];

    // stage 8 query rows and w_v
    for (int i = tid; i < 8 * 256; i += 512)
        qh_s[i] = g_qh[(b * 64 + q0) * 256 + i];
    for (int i = tid; i < 256; i += 512)
        wv_s[i] = w_v[i];

    // cp.async staging: tile t -> kh_s[(t&1)*64*KH_STRIDE].
    // 8 threads per row, thread j covers float4 indices j + i*8
    // -> float column j*4 + i*32  (max 28 + 224 = 252, in-bounds).
    const float* khg = &g_kh[(size_t)b * 512 * 256];
    const int sr  = tid >> 3;              // 0..63 row within tile
    const int sc4 = (tid & 7) * 4;         // float col base (16B aligned)
    // prefetch tiles 0 and 1
    #pragma unroll
    for (int pre = 0; pre < 2; ++pre) {
        float* dst = &kh_s[pre * 64 * KH_STRIDE];
        const float* src = &khg[(pre * 64 + sr) * 256];
        #pragma unroll
        for (int i = 0; i < 8; ++i)
            cp_async16(&dst[sr * KH_STRIDE + sc4 + i * 32], &src[sc4 + i * 32]);
        cp_async_commit();
    }

    float sc[8];

    #pragma unroll
    for (int t = 0; t < 8; ++t) {
        if (t < 7) cp_async_wait1(); else cp_async_wait0();
        __syncthreads();

        const float* khr = &kh_s[(t & 1) * 64 * KH_STRIDE + krow * KH_STRIDE];
        const float* qr  = &qh_s[qloc * 256];
        float s0 = 0.f, s1 = 0.f;
        #pragma unroll 8
        for (int h = 0; h < 256; h += 4) {
            float4 kv = *(const float4*)&khr[h];
            float4 qv = *(const float4*)&qr[h];
            float4 w4 = *(const float4*)&wv_s[h];
            s0 = fmaf(w4.x, tanh_fast(qv.x + kv.x), s0);
            s1 = fmaf(w4.y, tanh_fast(qv.y + kv.y), s1);
            s0 = fmaf(w4.z, tanh_fast(qv.z + kv.z), s0);
            s1 = fmaf(w4.w, tanh_fast(qv.w + kv.w), s1);
        }
        sc[t] = s0 + s1;

        __syncthreads();
        if (t < 6) {  // prefetch tile t+2 into the buffer just freed
            float* dst = &kh_s[(t & 1) * 64 * KH_STRIDE];
            const float* src = &khg[((t + 2) * 64 + sr) * 256];
            #pragma unroll
            for (int i = 0; i < 8; ++i)
                cp_async16(&dst[sr * KH_STRIDE + sc4 + i * 32], &src[sc4 + i * 32]);
            cp_async_commit();
        }
    }

    // mask + local max
    float m = -3e38f;
    #pragma unroll
    for (int t = 0; t < 8; ++t) {
        int k = t * 64 + krow;
        float v = sc[t];
        if (k >= vlen) v = -1e30f;
        sc[t] = v;
        m = fmaxf(m, v);
    }
    #pragma unroll
    for (int o = 16; o; o >>= 1) m = fmaxf(m, __shfl_xor_sync(0xffffffffu, m, o));
    if (lane == 0) red_s[qloc * 2 + sub] = m;
    __syncthreads();
    const float mall = fmaxf(red_s[qloc * 2], red_s[qloc * 2 + 1]);

    float p[8];
    float sum = 0.f;
    #pragma unroll
    for (int t = 0; t < 8; ++t) {
        p[t] = ex2_fast((sc[t] - mall) * 1.4426950408889634f);
        sum += p[t];
    }
    #pragma unroll
    for (int o = 16; o; o >>= 1) sum += __shfl_xor_sync(0xffffffffu, sum, o);
    if (lane == 0) red_s[16 + qloc * 2 + sub] = sum;
    __syncthreads();
    const float inv = rcp_fast(red_s[16 + qloc * 2] + red_s[16 + qloc * 2 + 1]);

    #pragma unroll
    for (int t = 0; t < 8; ++t)
        attn_s[qloc * 512 + t * 64 + krow] = p[t] * inv;
    __syncthreads();

    // ------ output: out[b, q0+qq, v] = sum_k attn[qq][k] * values[b,k,v] ------
    const int half = tid >> 8;          // 0: q0..q0+3, 1: q0+4..q0+7
    const int v    = tid & 255;
    const float* vp = values + (size_t)b * 512 * 256 + v;
    const float* a0 = &attn_s[(half * 4 + 0) * 512];
    const float* a1 = a0 + 512;
    const float* a2 = a1 + 512;
    const float* a3 = a2 + 512;
    float o0 = 0.f, o1 = 0.f, o2 = 0.f, o3 = 0.f;
    #pragma unroll 4
    for (int k = 0; k < vlen; ++k) {
        float vv = vp[(size_t)k * 256];
        o0 = fmaf(a0[k], vv, o0);
        o1 = fmaf(a1[k], vv, o1);
        o2 = fmaf(a2[k], vv, o2);
        o3 = fmaf(a3[k], vv, o3);
    }
    float* op = out + ((size_t)b * 64 + q0 + half * 4) * 256 + v;
    op[0]   = o0;
    op[256] = o1;
    op[512] = o2;
    op[768] = o3;
}

// ----------------------------------------------------------------------------
extern "C" void kernel_launch(void* const* d_in, const int* in_sizes, int n_in,
                              void* d_out, int out_size) {
    (void)in_sizes; (void)n_in; (void)out_size;
    const float* queries = (const float*)d_in[0];   // [16,64,256]
    const float* keys    = (const float*)d_in[1];   // [16,512,256]
    const float* values  = (const float*)d_in[2];   // [16,512,256]
    const int*   vlens   = (const int*)  d_in[3];   // [16]
    const float* Wq      = (const float*)d_in[4];   // [256,256]
    const float* Wk      = (const float*)d_in[5];   // [256,256]
    const float* wv      = (const float*)d_in[6];   // [256]
    float* out = (float*)d_out;                     // [16,64,256]

    float *qh = nullptr, *kh = nullptr;
    cudaGetSymbolAddress((void**)&qh, g_qh);
    cudaGetSymbolAddress((void**)&kh, g_kh);

    cudaFuncSetAttribute(attn_kernel,
                         cudaFuncAttributeMaxDynamicSharedMemorySize,
                         ATTN_SMEM_BYTES);

    proj_kernel<<<dim3(2, 72), 256>>>(queries, keys, Wq, Wk, qh, kh);
    attn_kernel<<<128, 512, ATTN_SMEM_BYTES>>>(values, vlens, wv, out);
}